// round 14
// baseline (speedup 1.0000x reference)
#include <cuda_runtime.h>
#include <math.h>

#define N_ENT   100000
#define D       128
#define N_EDGES 1600000
#define BATCH   8192
#define EPS     1e-5f

#define SLACK    128
#define BM_WORDS 3125              // ceil(100000/32)

#define FILL_BLKS 148
#define STAT_BLKS 296
#define K2_BLKS   (FILL_BLKS + STAT_BLKS)   // 444 -> single wave @3/SM

#define TROWS 32                   // rows per tile block (2 rows per warp)
#define TILE_BLKS (BATCH / TROWS)  // 256 -> single wave @2/SM

// output layout: [loss(1)] [age(8192*7)] [gender(8192)] [occ(8192*21)]
#define OFF_AGE  1
#define OFF_G    (1 + BATCH * 7)
#define OFF_OCC  (OFF_G + BATCH)

// ------------- persistent device state (zero-init; self-maintained) -------
__device__ __align__(16) float g_colsum[D];
__device__ __align__(16) float g_colsq[D];
__device__ unsigned g_bm[BM_WORDS];
__device__ int   g_slotmark[N_ENT];        // == epoch tag when claimed this replay
__device__ int   g_slotnum[N_ENT];         // compact slot for claimed nodes
__device__ int   g_epoch;                  // bumped by last tile block
__device__ int   g_nslots;
__device__ int   g_prep_cnt;               // fill-block prep barrier
__device__ int   g_cur[BATCH];             // slot cursor == degree
__device__ int   g_ebufc[BATCH * SLACK];   // compact buckets (4 MB)
__device__ float g_loss;                   // BCE accumulator
__device__ int   g_done;                   // tile completion counter

// ====== K1: prep (by fill blocks) + edge fill  ||  colstats ===============
__global__ void __launch_bounds__(512, 3)
k_statsfill(const float* __restrict__ E,
            const int* __restrict__ src, const int* __restrict__ dst,
            const int* __restrict__ nb) {
    __shared__ __align__(16) char s_raw[12544];
    int tid = threadIdx.x;

    if (blockIdx.x < FILL_BLKS) {
        // ---- phase A: cooperative prep (claim slots + bitmask) ----
        {
            const int per = (BATCH + FILL_BLKS - 1) / FILL_BLKS;   // 56
            int i0 = blockIdx.x * per;
            int i1 = i0 + per; if (i1 > BATCH) i1 = BATCH;
            int tag = g_epoch + 1;
            for (int i = i0 + tid; i < i1; i += 512) {
                int node = nb[i];
                atomicOr(&g_bm[node >> 5], 1u << (node & 31));
                int old = atomicExch(&g_slotmark[node], tag);
                if (old != tag) {              // first claimer this replay
                    int s = atomicAdd(&g_nslots, 1);
                    g_slotnum[node] = s;
                }
            }
            __threadfence();
            __syncthreads();
            if (tid == 0) {
                atomicAdd(&g_prep_cnt, 1);
                while (*(volatile int*)&g_prep_cnt < FILL_BLKS) __nanosleep(32);
            }
            __syncthreads();
            __threadfence();                   // acquire: see all preps
        }

        // ---- phase B: filtered edge fill into compact buckets ----
        unsigned* s_bm = (unsigned*)s_raw;
        for (int i = tid; i < BM_WORDS; i += 512) s_bm[i] = g_bm[i];
        __syncthreads();
        const int4* dst4 = (const int4*)dst;
        const int stride = FILL_BLKS * 512;
        for (int idx4 = blockIdx.x * 512 + tid; idx4 < N_EDGES / 4; idx4 += stride) {
            int4 d4 = dst4[idx4];
            int e = idx4 * 4;
            int dd[4] = {d4.x, d4.y, d4.z, d4.w};
#pragma unroll
            for (int k = 0; k < 4; k++) {
                int d = dd[k];
                if ((s_bm[d >> 5] >> (d & 31)) & 1u) {
                    int s = g_slotnum[d];
                    int p = atomicAdd(&g_cur[s], 1);
                    if (p < SLACK) g_ebufc[s * SLACK + p] = src[e + k];
                }
            }
        }
    } else {
        // ---- column stats partials -> float atomics (prep-independent) ----
        int cb = blockIdx.x - FILL_BLKS;
        const int rows_per = (N_ENT + STAT_BLKS - 1) / STAT_BLKS;   // 338
        int r0 = cb * rows_per;
        int r1 = r0 + rows_per; if (r1 > N_ENT) r1 = N_ENT;
        int c4 = tid & 31;
        int grp = tid >> 5;                // 0..15
        const float4* E4 = (const float4*)E;
        float4 s = make_float4(0.f, 0.f, 0.f, 0.f);
        float4 q = make_float4(0.f, 0.f, 0.f, 0.f);
#pragma unroll 8
        for (int r = r0 + grp; r < r1; r += 16) {
            float4 v = E4[(size_t)r * 32 + c4];
            s.x += v.x; s.y += v.y; s.z += v.z; s.w += v.w;
            q.x += v.x * v.x; q.y += v.y * v.y;
            q.z += v.z * v.z; q.w += v.w * v.w;
        }
        float4* s_red = (float4*)s_raw;    // [512] float4
        s_red[grp * 32 + c4] = s;
        __syncthreads();
        if (tid < 32) {
            float4 a = make_float4(0.f, 0.f, 0.f, 0.f);
#pragma unroll
            for (int g = 0; g < 16; g++) {
                float4 v = s_red[g * 32 + tid];
                a.x += v.x; a.y += v.y; a.z += v.z; a.w += v.w;
            }
            atomicAdd(&g_colsum[tid * 4 + 0], a.x);
            atomicAdd(&g_colsum[tid * 4 + 1], a.y);
            atomicAdd(&g_colsum[tid * 4 + 2], a.z);
            atomicAdd(&g_colsum[tid * 4 + 3], a.w);
        }
        __syncthreads();
        s_red[grp * 32 + c4] = q;
        __syncthreads();
        if (tid < 32) {
            float4 a = make_float4(0.f, 0.f, 0.f, 0.f);
#pragma unroll
            for (int g = 0; g < 16; g++) {
                float4 v = s_red[g * 32 + tid];
                a.x += v.x; a.y += v.y; a.z += v.z; a.w += v.w;
            }
            atomicAdd(&g_colsq[tid * 4 + 0], a.x);
            atomicAdd(&g_colsq[tid * 4 + 1], a.y);
            atomicAdd(&g_colsq[tid * 4 + 2], a.z);
            atomicAdd(&g_colsq[tid * 4 + 3], a.w);
        }
    }
}

// ======== K2: fused gather + affine + GEMM + heads + loss + cleanup =======
__global__ void __launch_bounds__(512, 2)
k_tiles(const float* __restrict__ E,
        const float* __restrict__ gamma, const float* __restrict__ beta,
        const float* __restrict__ W_gnn, const float* __restrict__ b_gnn,
        const float* __restrict__ Wg,    const float* __restrict__ bg,
        const float* __restrict__ Wage,  const float* __restrict__ bage,
        const float* __restrict__ Wocc,  const float* __restrict__ bocc,
        const int* __restrict__ nb,      const int* __restrict__ gender,
        float* __restrict__ out) {
    __shared__ __align__(16) float sA[TROWS * D];     // 16 KB
    __shared__ __align__(16) float sU[TROWS * D];     // 16 KB
    __shared__ __align__(16) float sW[D * 32];        // 16 KB fused head weights
    __shared__ float s_scale[D];
    __shared__ float s_shift[D];
    __shared__ float s_bce[TROWS];
    __shared__ int   s_last;
    float4* sA4 = (float4*)sA;
    const int tid = threadIdx.x;
    const int lane = tid & 31;
    const int widx = tid >> 5;             // 0..15

    if (tid < D) {
        const float invn = 1.0f / (float)N_ENT;
        float mean = g_colsum[tid] * invn;
        float var = g_colsq[tid] * invn - mean * mean;
        float sc = rsqrtf(var + EPS) * gamma[tid];
        s_scale[tid] = sc;
        s_shift[tid] = beta[tid] - mean * sc;
    }
    // stage fused head-weight matrix [D][32]: col 0=gender, 1..7=age, 8..28=occ
    for (int i = tid; i < D * 32; i += 512) {
        int k = i >> 5, c = i & 31;
        float w;
        if (c == 0)       w = Wg[k];
        else if (c < 8)   w = Wage[k * 7 + (c - 1)];
        else if (c < 29)  w = Wocc[k * 21 + (c - 8)];
        else              w = 0.0f;
        sW[i] = w;
    }
    __syncthreads();

    const int row0 = blockIdx.x * TROWS;
    const float4* E4 = (const float4*)E;

    // gather raw neighbor sum + affine: each warp produces 2 rows (MLP-4 each)
#pragma unroll
    for (int r2 = 0; r2 < 2; r2++) {
        int lr = widx * 2 + r2;            // local row 0..31
        int row = row0 + lr;
        int node = nb[row];
        int s = g_slotnum[node];
        int deg = g_cur[s];
        int dc = deg < SLACK ? deg : SLACK;
        const int* lst = &g_ebufc[s * SLACK];
        float4 acc = make_float4(0.f, 0.f, 0.f, 0.f);
        int i = 0;
        for (; i + 4 <= dc; i += 4) {
            int i0 = lst[i + 0], i1 = lst[i + 1];
            int i2 = lst[i + 2], i3 = lst[i + 3];
            float4 a = E4[(size_t)i0 * 32 + lane];
            float4 b = E4[(size_t)i1 * 32 + lane];
            float4 c = E4[(size_t)i2 * 32 + lane];
            float4 d = E4[(size_t)i3 * 32 + lane];
            acc.x += a.x + b.x + c.x + d.x;
            acc.y += a.y + b.y + c.y + d.y;
            acc.z += a.z + b.z + c.z + d.z;
            acc.w += a.w + b.w + c.w + d.w;
        }
        for (; i < dc; i++) {
            int sv = lst[i];
            float4 a = E4[(size_t)sv * 32 + lane];
            acc.x += a.x; acc.y += a.y; acc.z += a.z; acc.w += a.w;
        }
        float fdeg = (float)deg;
        float inv = 1.0f / fmaxf(fdeg, 1.0f);
        float4 sc4 = ((const float4*)s_scale)[lane];
        float4 sh4 = ((const float4*)s_shift)[lane];
        float4 o;
        o.x = (acc.x * sc4.x + fdeg * sh4.x) * inv;
        o.y = (acc.y * sc4.y + fdeg * sh4.y) * inv;
        o.z = (acc.z * sc4.z + fdeg * sh4.z) * inv;
        o.w = (acc.w * sc4.w + fdeg * sh4.w) * inv;
        sA4[lr * 32 + lane] = o;
    }
    __syncthreads();

    // GEMM: col = tid&127, grp = tid>>7 (0..3): rows grp*8..grp*8+7
    // (w loads amortized over 8 rows -> half the LDG issue of TROWS=16)
    {
        int col = tid & 127;
        int grp = tid >> 7;
        float accg[8];
#pragma unroll
        for (int r = 0; r < 8; r++) accg[r] = 0.0f;
        for (int k = 0; k < D; k += 4) {
            float w0 = W_gnn[(k + 0) * D + col];
            float w1 = W_gnn[(k + 1) * D + col];
            float w2 = W_gnn[(k + 2) * D + col];
            float w3 = W_gnn[(k + 3) * D + col];
#pragma unroll
            for (int r = 0; r < 8; r++) {
                float4 a = *(const float4*)&sA[(grp * 8 + r) * D + k];
                accg[r] += a.x * w0 + a.y * w1 + a.z * w2 + a.w * w3;
            }
        }
        float bb = b_gnn[col];
#pragma unroll
        for (int r = 0; r < 8; r++)
            sU[(grp * 8 + r) * D + col] = fmaxf(accg[r] + bb, 0.0f);
    }
    __syncthreads();

    // heads as smem mini-GEMM: warp handles 2 rows, lane = head column
#pragma unroll
    for (int r2 = 0; r2 < 2; r2++) {
        int hrow = widx * 2 + r2;          // 0..31
        int hcol = lane;                   // 0..31 (29 used)
        const float4* u4 = (const float4*)&sU[hrow * D];
        float acc = 0.0f;
#pragma unroll
        for (int k4 = 0; k4 < D / 4; k4++) {
            float4 u = u4[k4];
            int k = k4 * 4;
            acc += u.x * sW[(k + 0) * 32 + hcol]
                 + u.y * sW[(k + 1) * 32 + hcol]
                 + u.z * sW[(k + 2) * 32 + hcol]
                 + u.w * sW[(k + 3) * 32 + hcol];
        }
        int orow = row0 + hrow;
        if (hcol == 0) {
            float x = acc + bg[0];
            out[OFF_G + orow] = x;
            float z = (float)gender[orow];
            s_bce[hrow] = fmaxf(x, 0.0f) - x * z + log1pf(expf(-fabsf(x)));
        } else if (hcol < 8) {
            out[OFF_AGE + (size_t)orow * 7 + (hcol - 1)] = acc + bage[hcol - 1];
        } else if (hcol < 29) {
            out[OFF_OCC + (size_t)orow * 21 + (hcol - 8)] = acc + bocc[hcol - 8];
        }
    }
    __syncthreads();

    // block BCE partial -> global accumulator
    if (tid < 32) {
        float b2 = s_bce[tid];
#pragma unroll
        for (int off = 16; off; off >>= 1)
            b2 += __shfl_xor_sync(0xffffffffu, b2, off);
        if (tid == 0) atomicAdd(&g_loss, b2);
    }
    __syncthreads();

    // last block: finish loss + cleanup for next replay
    if (tid == 0) {
        __threadfence();
        s_last = (atomicAdd(&g_done, 1) == TILE_BLKS - 1);
    }
    __syncthreads();
    if (s_last) {
        if (tid == 0) {
            __threadfence();
            out[0] = *(volatile float*)&g_loss * (1.0f / (float)BATCH);
            g_loss = 0.0f;
            g_nslots = 0;
            g_prep_cnt = 0;
            g_epoch = g_epoch + 1;
            g_done = 0;
        }
        for (int i = tid; i < BATCH; i += 512) g_cur[i] = 0;
        for (int i = tid; i < BM_WORDS; i += 512) g_bm[i] = 0;
        if (tid < D) { g_colsum[tid] = 0.0f; g_colsq[tid] = 0.0f; }
        __threadfence();
    }
}

// ---------------- launch ----------------
extern "C" void kernel_launch(void* const* d_in, const int* in_sizes, int n_in,
                              void* d_out, int out_size) {
    const float* E      = (const float*)d_in[0];
    const float* gamma  = (const float*)d_in[1];
    const float* beta   = (const float*)d_in[2];
    const float* W_gnn  = (const float*)d_in[3];
    const float* b_gnn  = (const float*)d_in[4];
    const float* W_g    = (const float*)d_in[5];
    const float* b_g    = (const float*)d_in[6];
    const float* W_age  = (const float*)d_in[7];
    const float* b_age  = (const float*)d_in[8];
    const float* W_occ  = (const float*)d_in[9];
    const float* b_occ  = (const float*)d_in[10];
    const int*   src    = (const int*)d_in[11];
    const int*   dst    = (const int*)d_in[12];
    const int*   nb     = (const int*)d_in[13];
    const int*   gender = (const int*)d_in[14];
    float* out = (float*)d_out;

    k_statsfill<<<K2_BLKS, 512>>>(E, src, dst, nb);
    k_tiles<<<TILE_BLKS, 512>>>(E, gamma, beta, W_gnn, b_gnn, W_g, b_g,
                                W_age, b_age, W_occ, b_occ, nb, gender, out);
}

// round 15
// speedup vs baseline: 1.1417x; 1.1417x over previous
#include <cuda_runtime.h>
#include <math.h>

#define N_ENT   100000
#define D       128
#define N_EDGES 1600000
#define BATCH   8192
#define EPS     1e-5f

#define SLACK    128
#define BM_WORDS 3125              // ceil(100000/32)

#define FILL_BLKS 148
#define STAT_BLKS 296
#define K2_BLKS   (FILL_BLKS + STAT_BLKS)   // 444 -> single wave @3/SM

#define TROWS 16                   // rows per tile block (1 row per warp)
#define TILE_BLKS (BATCH / TROWS)  // 512

// output layout: [loss(1)] [age(8192*7)] [gender(8192)] [occ(8192*21)]
#define OFF_AGE  1
#define OFF_G    (1 + BATCH * 7)
#define OFF_OCC  (OFF_G + BATCH)

// packed fp32x2 FMA (sm_103a): d = a*b + c elementwise on 2-float packs
#define FMA_F32X2(d, a, b, c) \
    asm("fma.rn.f32x2 %0, %1, %2, %3;" : "=l"(d) : "l"(a), "l"(b), "l"(c))

// ------------- persistent device state (zero-init; self-maintained) -------
__device__ __align__(16) float g_colsum[D];
__device__ __align__(16) float g_colsq[D];
__device__ unsigned g_bm[BM_WORDS];
__device__ int   g_slotmark[N_ENT];        // == epoch tag when claimed this replay
__device__ int   g_slotnum[N_ENT];         // compact slot for claimed nodes
__device__ int   g_epoch;                  // bumped by last tile block
__device__ int   g_nslots;
__device__ int   g_prep_cnt;               // fill-block prep barrier
__device__ int   g_cur[BATCH];             // slot cursor == degree
__device__ int   g_ebufc[BATCH * SLACK];   // compact buckets (4 MB)
__device__ float g_loss;                   // BCE accumulator
__device__ int   g_done;                   // tile completion counter

// ====== K1: prep (by fill blocks) + edge fill  ||  colstats ===============
__global__ void __launch_bounds__(512, 3)
k_statsfill(const float* __restrict__ E,
            const int* __restrict__ src, const int* __restrict__ dst,
            const int* __restrict__ nb) {
    __shared__ __align__(16) char s_raw[12544];
    int tid = threadIdx.x;

    if (blockIdx.x < FILL_BLKS) {
        // ---- phase A: cooperative prep (claim slots + bitmask) ----
        {
            const int per = (BATCH + FILL_BLKS - 1) / FILL_BLKS;   // 56
            int i0 = blockIdx.x * per;
            int i1 = i0 + per; if (i1 > BATCH) i1 = BATCH;
            int tag = g_epoch + 1;
            for (int i = i0 + tid; i < i1; i += 512) {
                int node = nb[i];
                atomicOr(&g_bm[node >> 5], 1u << (node & 31));
                int old = atomicExch(&g_slotmark[node], tag);
                if (old != tag) {              // first claimer this replay
                    int s = atomicAdd(&g_nslots, 1);
                    g_slotnum[node] = s;
                }
            }
            __threadfence();
            __syncthreads();
            if (tid == 0) {
                atomicAdd(&g_prep_cnt, 1);
                while (*(volatile int*)&g_prep_cnt < FILL_BLKS) __nanosleep(32);
            }
            __syncthreads();
            __threadfence();                   // acquire: see all preps
        }

        // ---- phase B: filtered edge fill into compact buckets ----
        unsigned* s_bm = (unsigned*)s_raw;
        for (int i = tid; i < BM_WORDS; i += 512) s_bm[i] = g_bm[i];
        __syncthreads();
        const int4* dst4 = (const int4*)dst;
        const int stride = FILL_BLKS * 512;
        for (int idx4 = blockIdx.x * 512 + tid; idx4 < N_EDGES / 4; idx4 += stride) {
            int4 d4 = dst4[idx4];
            int e = idx4 * 4;
            int dd[4] = {d4.x, d4.y, d4.z, d4.w};
#pragma unroll
            for (int k = 0; k < 4; k++) {
                int d = dd[k];
                if ((s_bm[d >> 5] >> (d & 31)) & 1u) {
                    int s = g_slotnum[d];
                    int p = atomicAdd(&g_cur[s], 1);
                    if (p < SLACK) g_ebufc[s * SLACK + p] = src[e + k];
                }
            }
        }
    } else {
        // ---- column stats partials -> float atomics (prep-independent) ----
        int cb = blockIdx.x - FILL_BLKS;
        const int rows_per = (N_ENT + STAT_BLKS - 1) / STAT_BLKS;   // 338
        int r0 = cb * rows_per;
        int r1 = r0 + rows_per; if (r1 > N_ENT) r1 = N_ENT;
        int c4 = tid & 31;
        int grp = tid >> 5;                // 0..15
        const float4* E4 = (const float4*)E;
        float4 s = make_float4(0.f, 0.f, 0.f, 0.f);
        float4 q = make_float4(0.f, 0.f, 0.f, 0.f);
#pragma unroll 8
        for (int r = r0 + grp; r < r1; r += 16) {
            float4 v = E4[(size_t)r * 32 + c4];
            s.x += v.x; s.y += v.y; s.z += v.z; s.w += v.w;
            q.x += v.x * v.x; q.y += v.y * v.y;
            q.z += v.z * v.z; q.w += v.w * v.w;
        }
        float4* s_red = (float4*)s_raw;    // [512] float4
        s_red[grp * 32 + c4] = s;
        __syncthreads();
        if (tid < 32) {
            float4 a = make_float4(0.f, 0.f, 0.f, 0.f);
#pragma unroll
            for (int g = 0; g < 16; g++) {
                float4 v = s_red[g * 32 + tid];
                a.x += v.x; a.y += v.y; a.z += v.z; a.w += v.w;
            }
            atomicAdd(&g_colsum[tid * 4 + 0], a.x);
            atomicAdd(&g_colsum[tid * 4 + 1], a.y);
            atomicAdd(&g_colsum[tid * 4 + 2], a.z);
            atomicAdd(&g_colsum[tid * 4 + 3], a.w);
        }
        __syncthreads();
        s_red[grp * 32 + c4] = q;
        __syncthreads();
        if (tid < 32) {
            float4 a = make_float4(0.f, 0.f, 0.f, 0.f);
#pragma unroll
            for (int g = 0; g < 16; g++) {
                float4 v = s_red[g * 32 + tid];
                a.x += v.x; a.y += v.y; a.z += v.z; a.w += v.w;
            }
            atomicAdd(&g_colsq[tid * 4 + 0], a.x);
            atomicAdd(&g_colsq[tid * 4 + 1], a.y);
            atomicAdd(&g_colsq[tid * 4 + 2], a.z);
            atomicAdd(&g_colsq[tid * 4 + 3], a.w);
        }
    }
}

// ======== K2: fused gather + affine + GEMM(f32x2) + heads + loss ==========
__global__ void __launch_bounds__(512, 3)
k_tiles(const float* __restrict__ E,
        const float* __restrict__ gamma, const float* __restrict__ beta,
        const float* __restrict__ W_gnn, const float* __restrict__ b_gnn,
        const float* __restrict__ Wg,    const float* __restrict__ bg,
        const float* __restrict__ Wage,  const float* __restrict__ bage,
        const float* __restrict__ Wocc,  const float* __restrict__ bocc,
        const int* __restrict__ nb,      const int* __restrict__ gender,
        float* __restrict__ out) {
    // sAd: duplicated activations  sAd[row][2k] == sAd[row][2k+1] == a[row][k]
    __shared__ __align__(16) float sAd[TROWS * 2 * D]; // 16 KB
    __shared__ __align__(16) float sU[TROWS * D];      // 8 KB
    __shared__ __align__(16) float sW[D * 32];         // 16 KB fused head weights
    __shared__ float s_scale[D];
    __shared__ float s_shift[D];
    __shared__ float s_bce[TROWS];
    __shared__ int   s_last;
    const int tid = threadIdx.x;
    const int lane = tid & 31;
    const int widx = tid >> 5;             // 0..15

    if (tid < D) {
        const float invn = 1.0f / (float)N_ENT;
        float mean = g_colsum[tid] * invn;
        float var = g_colsq[tid] * invn - mean * mean;
        float sc = rsqrtf(var + EPS) * gamma[tid];
        s_scale[tid] = sc;
        s_shift[tid] = beta[tid] - mean * sc;
    }
    // stage fused head-weight matrix [D][32]: col 0=gender, 1..7=age, 8..28=occ
    for (int i = tid; i < D * 32; i += 512) {
        int k = i >> 5, c = i & 31;
        float w;
        if (c == 0)       w = Wg[k];
        else if (c < 8)   w = Wage[k * 7 + (c - 1)];
        else if (c < 29)  w = Wocc[k * 21 + (c - 8)];
        else              w = 0.0f;
        sW[i] = w;
    }
    __syncthreads();

    const int row0 = blockIdx.x * TROWS;
    const int row = row0 + widx;           // one row per warp
    const float4* E4 = (const float4*)E;

    // gather raw neighbor sum + affine (MLP-4), write DUPLICATED to sAd
    {
        int node = nb[row];
        int s = g_slotnum[node];
        int deg = g_cur[s];
        int dc = deg < SLACK ? deg : SLACK;
        const int* lst = &g_ebufc[s * SLACK];
        float4 acc = make_float4(0.f, 0.f, 0.f, 0.f);
        int i = 0;
        for (; i + 4 <= dc; i += 4) {
            int i0 = lst[i + 0], i1 = lst[i + 1];
            int i2 = lst[i + 2], i3 = lst[i + 3];
            float4 a = E4[(size_t)i0 * 32 + lane];
            float4 b = E4[(size_t)i1 * 32 + lane];
            float4 c = E4[(size_t)i2 * 32 + lane];
            float4 d = E4[(size_t)i3 * 32 + lane];
            acc.x += a.x + b.x + c.x + d.x;
            acc.y += a.y + b.y + c.y + d.y;
            acc.z += a.z + b.z + c.z + d.z;
            acc.w += a.w + b.w + c.w + d.w;
        }
        for (; i < dc; i++) {
            int sv = lst[i];
            float4 a = E4[(size_t)sv * 32 + lane];
            acc.x += a.x; acc.y += a.y; acc.z += a.z; acc.w += a.w;
        }
        float fdeg = (float)deg;
        float inv = 1.0f / fmaxf(fdeg, 1.0f);
        float4 sc4 = ((const float4*)s_scale)[lane];
        float4 sh4 = ((const float4*)s_shift)[lane];
        float ox = (acc.x * sc4.x + fdeg * sh4.x) * inv;
        float oy = (acc.y * sc4.y + fdeg * sh4.y) * inv;
        float oz = (acc.z * sc4.z + fdeg * sh4.z) * inv;
        float ow = (acc.w * sc4.w + fdeg * sh4.w) * inv;
        // duplicated store: lane covers k = lane*4..lane*4+3 -> 8 floats
        float4* dup4 = (float4*)&sAd[widx * 2 * D + lane * 8];
        dup4[0] = make_float4(ox, ox, oy, oy);
        dup4[1] = make_float4(oz, oz, ow, ow);
    }
    __syncthreads();

    // GEMM with packed f32x2: thread = (colpair cp 0..63, grp 0..7 -> 2 rows)
    {
        int cp = tid & 63;                 // column pair: cols 2cp, 2cp+1
        int grp = tid >> 6;                // 0..7: rows grp*2, grp*2+1
        unsigned long long acc0 = 0ull, acc1 = 0ull;   // {col2cp, col2cp+1} packs
        const float* wbase = &W_gnn[2 * cp];
        const unsigned long long* dupr0 =
            (const unsigned long long*)&sAd[(grp * 2 + 0) * 2 * D];
        const unsigned long long* dupr1 =
            (const unsigned long long*)&sAd[(grp * 2 + 1) * 2 * D];
        for (int k = 0; k < D; k += 4) {
            unsigned long long w0 = *(const unsigned long long*)&wbase[(k + 0) * D];
            unsigned long long w1 = *(const unsigned long long*)&wbase[(k + 1) * D];
            unsigned long long w2 = *(const unsigned long long*)&wbase[(k + 2) * D];
            unsigned long long w3 = *(const unsigned long long*)&wbase[(k + 3) * D];
            // row grp*2
            ulonglong2 qa = *(const ulonglong2*)&dupr0[k];       // {a0,a0},{a1,a1}
            ulonglong2 qb = *(const ulonglong2*)&dupr0[k + 2];   // {a2,a2},{a3,a3}
            FMA_F32X2(acc0, w0, qa.x, acc0);
            FMA_F32X2(acc0, w1, qa.y, acc0);
            FMA_F32X2(acc0, w2, qb.x, acc0);
            FMA_F32X2(acc0, w3, qb.y, acc0);
            // row grp*2+1
            ulonglong2 qc = *(const ulonglong2*)&dupr1[k];
            ulonglong2 qd = *(const ulonglong2*)&dupr1[k + 2];
            FMA_F32X2(acc1, w0, qc.x, acc1);
            FMA_F32X2(acc1, w1, qc.y, acc1);
            FMA_F32X2(acc1, w2, qd.x, acc1);
            FMA_F32X2(acc1, w3, qd.y, acc1);
        }
        float2 bb = *(const float2*)&b_gnn[2 * cp];
        float l0, h0, l1, h1;
        asm("mov.b64 {%0, %1}, %2;" : "=f"(l0), "=f"(h0) : "l"(acc0));
        asm("mov.b64 {%0, %1}, %2;" : "=f"(l1), "=f"(h1) : "l"(acc1));
        float2* su2a = (float2*)&sU[(grp * 2 + 0) * D + 2 * cp];
        float2* su2b = (float2*)&sU[(grp * 2 + 1) * D + 2 * cp];
        *su2a = make_float2(fmaxf(l0 + bb.x, 0.0f), fmaxf(h0 + bb.y, 0.0f));
        *su2b = make_float2(fmaxf(l1 + bb.x, 0.0f), fmaxf(h1 + bb.y, 0.0f));
    }
    __syncthreads();

    // heads as smem mini-GEMM: thread = (hrow = widx, hcol = lane)
    {
        int hcol = lane;                   // 0..31 (29 used)
        int hrow = widx;                   // 0..15
        const float4* u4 = (const float4*)&sU[hrow * D];
        float acc = 0.0f;
#pragma unroll
        for (int k4 = 0; k4 < D / 4; k4++) {
            float4 u = u4[k4];
            int k = k4 * 4;
            acc += u.x * sW[(k + 0) * 32 + hcol]
                 + u.y * sW[(k + 1) * 32 + hcol]
                 + u.z * sW[(k + 2) * 32 + hcol]
                 + u.w * sW[(k + 3) * 32 + hcol];
        }
        int orow = row0 + hrow;
        if (hcol == 0) {
            float x = acc + bg[0];
            out[OFF_G + orow] = x;
            float z = (float)gender[orow];
            s_bce[hrow] = fmaxf(x, 0.0f) - x * z + log1pf(expf(-fabsf(x)));
        } else if (hcol < 8) {
            out[OFF_AGE + (size_t)orow * 7 + (hcol - 1)] = acc + bage[hcol - 1];
        } else if (hcol < 29) {
            out[OFF_OCC + (size_t)orow * 21 + (hcol - 8)] = acc + bocc[hcol - 8];
        }
    }
    __syncthreads();

    // block BCE partial -> global accumulator
    if (tid < 16) {
        float b2 = s_bce[tid];
#pragma unroll
        for (int off = 8; off; off >>= 1)
            b2 += __shfl_xor_sync(0x0000ffffu, b2, off);
        if (tid == 0) atomicAdd(&g_loss, b2);
    }
    __syncthreads();

    // last block: finish loss + cleanup for next replay
    if (tid == 0) {
        __threadfence();
        s_last = (atomicAdd(&g_done, 1) == TILE_BLKS - 1);
    }
    __syncthreads();
    if (s_last) {
        if (tid == 0) {
            __threadfence();
            out[0] = *(volatile float*)&g_loss * (1.0f / (float)BATCH);
            g_loss = 0.0f;
            g_nslots = 0;
            g_prep_cnt = 0;
            g_epoch = g_epoch + 1;
            g_done = 0;
        }
        for (int i = tid; i < BATCH; i += 512) g_cur[i] = 0;
        for (int i = tid; i < BM_WORDS; i += 512) g_bm[i] = 0;
        if (tid < D) { g_colsum[tid] = 0.0f; g_colsq[tid] = 0.0f; }
        __threadfence();
    }
}

// ---------------- launch ----------------
extern "C" void kernel_launch(void* const* d_in, const int* in_sizes, int n_in,
                              void* d_out, int out_size) {
    const float* E      = (const float*)d_in[0];
    const float* gamma  = (const float*)d_in[1];
    const float* beta   = (const float*)d_in[2];
    const float* W_gnn  = (const float*)d_in[3];
    const float* b_gnn  = (const float*)d_in[4];
    const float* W_g    = (const float*)d_in[5];
    const float* b_g    = (const float*)d_in[6];
    const float* W_age  = (const float*)d_in[7];
    const float* b_age  = (const float*)d_in[8];
    const float* W_occ  = (const float*)d_in[9];
    const float* b_occ  = (const float*)d_in[10];
    const int*   src    = (const int*)d_in[11];
    const int*   dst    = (const int*)d_in[12];
    const int*   nb     = (const int*)d_in[13];
    const int*   gender = (const int*)d_in[14];
    float* out = (float*)d_out;

    k_statsfill<<<K2_BLKS, 512>>>(E, src, dst, nb);
    k_tiles<<<TILE_BLKS, 512>>>(E, gamma, beta, W_gnn, b_gnn, W_g, b_g,
                                W_age, b_age, W_occ, b_occ, nb, gender, out);
}

// round 16
// speedup vs baseline: 1.2203x; 1.0688x over previous
#include <cuda_runtime.h>
#include <math.h>

#define N_ENT   100000
#define D       128
#define N_EDGES 1600000
#define BATCH   8192
#define EPS     1e-5f

#define SLACK    128
#define BM_WORDS 3125              // ceil(100000/32)

#define FILL_BLKS 148
#define STAT_BLKS 296
#define K2_BLKS   (FILL_BLKS + STAT_BLKS)   // 444 -> single wave @3/SM

#define TNT   1024                 // k_tiles threads
#define TROWS 32                   // rows per tile block (1 row per warp)
#define TILE_BLKS (BATCH / TROWS)  // 256 -> single wave @2/SM, 64 warps/SM

// output layout: [loss(1)] [age(8192*7)] [gender(8192)] [occ(8192*21)]
#define OFF_AGE  1
#define OFF_G    (1 + BATCH * 7)
#define OFF_OCC  (OFF_G + BATCH)

// ------------- persistent device state (zero-init; self-maintained) -------
__device__ __align__(16) float g_colsum[D];
__device__ __align__(16) float g_colsq[D];
__device__ unsigned g_bm[BM_WORDS];
__device__ int   g_slotmark[N_ENT];        // == epoch tag when claimed this replay
__device__ int   g_slotnum[N_ENT];         // compact slot for claimed nodes
__device__ int   g_epoch;                  // bumped by last tile block
__device__ int   g_nslots;
__device__ int   g_prep_cnt;               // fill-block prep barrier
__device__ int   g_cur[BATCH];             // slot cursor == degree
__device__ int   g_ebufc[BATCH * SLACK];   // compact buckets (4 MB)
__device__ float g_loss;                   // BCE accumulator
__device__ int   g_done;                   // tile completion counter

// ====== K1: prep (by fill blocks) + edge fill  ||  colstats ===============
__global__ void __launch_bounds__(512, 3)
k_statsfill(const float* __restrict__ E,
            const int* __restrict__ src, const int* __restrict__ dst,
            const int* __restrict__ nb) {
    __shared__ __align__(16) char s_raw[12544];
    int tid = threadIdx.x;

    if (blockIdx.x < FILL_BLKS) {
        // ---- phase A: cooperative prep (claim slots + bitmask) ----
        {
            const int per = (BATCH + FILL_BLKS - 1) / FILL_BLKS;   // 56
            int i0 = blockIdx.x * per;
            int i1 = i0 + per; if (i1 > BATCH) i1 = BATCH;
            int tag = g_epoch + 1;
            for (int i = i0 + tid; i < i1; i += 512) {
                int node = nb[i];
                atomicOr(&g_bm[node >> 5], 1u << (node & 31));
                int old = atomicExch(&g_slotmark[node], tag);
                if (old != tag) {              // first claimer this replay
                    int s = atomicAdd(&g_nslots, 1);
                    g_slotnum[node] = s;
                }
            }
            __threadfence();
            __syncthreads();
            if (tid == 0) {
                atomicAdd(&g_prep_cnt, 1);
                while (*(volatile int*)&g_prep_cnt < FILL_BLKS) __nanosleep(32);
            }
            __syncthreads();
            __threadfence();                   // acquire: see all preps
        }

        // ---- phase B: filtered edge fill into compact buckets ----
        unsigned* s_bm = (unsigned*)s_raw;
        for (int i = tid; i < BM_WORDS; i += 512) s_bm[i] = g_bm[i];
        __syncthreads();
        const int4* dst4 = (const int4*)dst;
        const int stride = FILL_BLKS * 512;
        for (int idx4 = blockIdx.x * 512 + tid; idx4 < N_EDGES / 4; idx4 += stride) {
            int4 d4 = dst4[idx4];
            int e = idx4 * 4;
            int dd[4] = {d4.x, d4.y, d4.z, d4.w};
#pragma unroll
            for (int k = 0; k < 4; k++) {
                int d = dd[k];
                if ((s_bm[d >> 5] >> (d & 31)) & 1u) {
                    int s = g_slotnum[d];
                    int p = atomicAdd(&g_cur[s], 1);
                    if (p < SLACK) g_ebufc[s * SLACK + p] = src[e + k];
                }
            }
        }
    } else {
        // ---- column stats partials -> float atomics (prep-independent) ----
        int cb = blockIdx.x - FILL_BLKS;
        const int rows_per = (N_ENT + STAT_BLKS - 1) / STAT_BLKS;   // 338
        int r0 = cb * rows_per;
        int r1 = r0 + rows_per; if (r1 > N_ENT) r1 = N_ENT;
        int c4 = tid & 31;
        int grp = tid >> 5;                // 0..15
        const float4* E4 = (const float4*)E;
        float4 s = make_float4(0.f, 0.f, 0.f, 0.f);
        float4 q = make_float4(0.f, 0.f, 0.f, 0.f);
#pragma unroll 8
        for (int r = r0 + grp; r < r1; r += 16) {
            float4 v = E4[(size_t)r * 32 + c4];
            s.x += v.x; s.y += v.y; s.z += v.z; s.w += v.w;
            q.x += v.x * v.x; q.y += v.y * v.y;
            q.z += v.z * v.z; q.w += v.w * v.w;
        }
        float4* s_red = (float4*)s_raw;    // [512] float4
        s_red[grp * 32 + c4] = s;
        __syncthreads();
        if (tid < 32) {
            float4 a = make_float4(0.f, 0.f, 0.f, 0.f);
#pragma unroll
            for (int g = 0; g < 16; g++) {
                float4 v = s_red[g * 32 + tid];
                a.x += v.x; a.y += v.y; a.z += v.z; a.w += v.w;
            }
            atomicAdd(&g_colsum[tid * 4 + 0], a.x);
            atomicAdd(&g_colsum[tid * 4 + 1], a.y);
            atomicAdd(&g_colsum[tid * 4 + 2], a.z);
            atomicAdd(&g_colsum[tid * 4 + 3], a.w);
        }
        __syncthreads();
        s_red[grp * 32 + c4] = q;
        __syncthreads();
        if (tid < 32) {
            float4 a = make_float4(0.f, 0.f, 0.f, 0.f);
#pragma unroll
            for (int g = 0; g < 16; g++) {
                float4 v = s_red[g * 32 + tid];
                a.x += v.x; a.y += v.y; a.z += v.z; a.w += v.w;
            }
            atomicAdd(&g_colsq[tid * 4 + 0], a.x);
            atomicAdd(&g_colsq[tid * 4 + 1], a.y);
            atomicAdd(&g_colsq[tid * 4 + 2], a.z);
            atomicAdd(&g_colsq[tid * 4 + 3], a.w);
        }
    }
}

// ======== K2: fused gather + affine + GEMM + heads + loss + cleanup =======
__global__ void __launch_bounds__(TNT, 2)
k_tiles(const float* __restrict__ E,
        const float* __restrict__ gamma, const float* __restrict__ beta,
        const float* __restrict__ W_gnn, const float* __restrict__ b_gnn,
        const float* __restrict__ Wg,    const float* __restrict__ bg,
        const float* __restrict__ Wage,  const float* __restrict__ bage,
        const float* __restrict__ Wocc,  const float* __restrict__ bocc,
        const int* __restrict__ nb,      const int* __restrict__ gender,
        float* __restrict__ out) {
    __shared__ __align__(16) float sA[TROWS * D];     // 16 KB
    __shared__ __align__(16) float sU[TROWS * D];     // 16 KB
    __shared__ __align__(16) float sW[D * 32];        // 16 KB fused head weights
    __shared__ float s_scale[D];
    __shared__ float s_shift[D];
    __shared__ float s_bce[TROWS];
    __shared__ int   s_last;
    float4* sA4 = (float4*)sA;
    const int tid = threadIdx.x;
    const int lane = tid & 31;
    const int widx = tid >> 5;             // 0..31

    if (tid < D) {
        const float invn = 1.0f / (float)N_ENT;
        float mean = g_colsum[tid] * invn;
        float var = g_colsq[tid] * invn - mean * mean;
        float sc = rsqrtf(var + EPS) * gamma[tid];
        s_scale[tid] = sc;
        s_shift[tid] = beta[tid] - mean * sc;
    }
    // stage fused head-weight matrix [D][32]: col 0=gender, 1..7=age, 8..28=occ
    for (int i = tid; i < D * 32; i += TNT) {
        int k = i >> 5, c = i & 31;
        float w;
        if (c == 0)       w = Wg[k];
        else if (c < 8)   w = Wage[k * 7 + (c - 1)];
        else if (c < 29)  w = Wocc[k * 21 + (c - 8)];
        else              w = 0.0f;
        sW[i] = w;
    }
    __syncthreads();

    const int row0 = blockIdx.x * TROWS;
    const int row = row0 + widx;           // one row per warp
    const float4* E4 = (const float4*)E;

    // gather raw neighbor sum + affine (MLP-4)
    {
        int node = nb[row];
        int s = g_slotnum[node];
        int deg = g_cur[s];
        int dc = deg < SLACK ? deg : SLACK;
        const int* lst = &g_ebufc[s * SLACK];
        float4 acc = make_float4(0.f, 0.f, 0.f, 0.f);
        int i = 0;
        for (; i + 4 <= dc; i += 4) {
            int i0 = lst[i + 0], i1 = lst[i + 1];
            int i2 = lst[i + 2], i3 = lst[i + 3];
            float4 a = E4[(size_t)i0 * 32 + lane];
            float4 b = E4[(size_t)i1 * 32 + lane];
            float4 c = E4[(size_t)i2 * 32 + lane];
            float4 d = E4[(size_t)i3 * 32 + lane];
            acc.x += a.x + b.x + c.x + d.x;
            acc.y += a.y + b.y + c.y + d.y;
            acc.z += a.z + b.z + c.z + d.z;
            acc.w += a.w + b.w + c.w + d.w;
        }
        for (; i < dc; i++) {
            int sv = lst[i];
            float4 a = E4[(size_t)sv * 32 + lane];
            acc.x += a.x; acc.y += a.y; acc.z += a.z; acc.w += a.w;
        }
        float fdeg = (float)deg;
        float inv = 1.0f / fmaxf(fdeg, 1.0f);
        float4 sc4 = ((const float4*)s_scale)[lane];
        float4 sh4 = ((const float4*)s_shift)[lane];
        float4 o;
        o.x = (acc.x * sc4.x + fdeg * sh4.x) * inv;
        o.y = (acc.y * sc4.y + fdeg * sh4.y) * inv;
        o.z = (acc.z * sc4.z + fdeg * sh4.z) * inv;
        o.w = (acc.w * sc4.w + fdeg * sh4.w) * inv;
        sA4[widx * 32 + lane] = o;
    }
    __syncthreads();

    // GEMM: col = tid&127, grp = tid>>7 (0..7): rows grp*4..grp*4+3
    {
        int col = tid & 127;
        int grp = tid >> 7;
        float accg[4] = {0.f, 0.f, 0.f, 0.f};
        for (int k = 0; k < D; k += 4) {
            float w0 = W_gnn[(k + 0) * D + col];
            float w1 = W_gnn[(k + 1) * D + col];
            float w2 = W_gnn[(k + 2) * D + col];
            float w3 = W_gnn[(k + 3) * D + col];
#pragma unroll
            for (int r = 0; r < 4; r++) {
                float4 a = *(const float4*)&sA[(grp * 4 + r) * D + k];
                accg[r] += a.x * w0 + a.y * w1 + a.z * w2 + a.w * w3;
            }
        }
        float bb = b_gnn[col];
#pragma unroll
        for (int r = 0; r < 4; r++)
            sU[(grp * 4 + r) * D + col] = fmaxf(accg[r] + bb, 0.0f);
    }
    __syncthreads();

    // heads as smem mini-GEMM: thread = (hrow = widx, hcol = lane)
    {
        int hcol = lane;                   // 0..31 (29 used)
        int hrow = widx;                   // 0..31
        const float4* u4 = (const float4*)&sU[hrow * D];
        float acc = 0.0f;
#pragma unroll
        for (int k4 = 0; k4 < D / 4; k4++) {
            float4 u = u4[k4];
            int k = k4 * 4;
            acc += u.x * sW[(k + 0) * 32 + hcol]
                 + u.y * sW[(k + 1) * 32 + hcol]
                 + u.z * sW[(k + 2) * 32 + hcol]
                 + u.w * sW[(k + 3) * 32 + hcol];
        }
        int orow = row0 + hrow;
        if (hcol == 0) {
            float x = acc + bg[0];
            out[OFF_G + orow] = x;
            float z = (float)gender[orow];
            s_bce[hrow] = fmaxf(x, 0.0f) - x * z + log1pf(expf(-fabsf(x)));
        } else if (hcol < 8) {
            out[OFF_AGE + (size_t)orow * 7 + (hcol - 1)] = acc + bage[hcol - 1];
        } else if (hcol < 29) {
            out[OFF_OCC + (size_t)orow * 21 + (hcol - 8)] = acc + bocc[hcol - 8];
        }
    }
    __syncthreads();

    // block BCE partial -> global accumulator
    if (tid < 32) {
        float b2 = s_bce[tid];
#pragma unroll
        for (int off = 16; off; off >>= 1)
            b2 += __shfl_xor_sync(0xffffffffu, b2, off);
        if (tid == 0) atomicAdd(&g_loss, b2);
    }
    __syncthreads();

    // last block: finish loss + cleanup for next replay
    if (tid == 0) {
        __threadfence();
        s_last = (atomicAdd(&g_done, 1) == TILE_BLKS - 1);
    }
    __syncthreads();
    if (s_last) {
        if (tid == 0) {
            __threadfence();
            out[0] = *(volatile float*)&g_loss * (1.0f / (float)BATCH);
            g_loss = 0.0f;
            g_nslots = 0;
            g_prep_cnt = 0;
            g_epoch = g_epoch + 1;
            g_done = 0;
        }
        for (int i = tid; i < BATCH; i += TNT) g_cur[i] = 0;
        for (int i = tid; i < BM_WORDS; i += TNT) g_bm[i] = 0;
        if (tid < D) { g_colsum[tid] = 0.0f; g_colsq[tid] = 0.0f; }
        __threadfence();
    }
}

// ---------------- launch ----------------
extern "C" void kernel_launch(void* const* d_in, const int* in_sizes, int n_in,
                              void* d_out, int out_size) {
    const float* E      = (const float*)d_in[0];
    const float* gamma  = (const float*)d_in[1];
    const float* beta   = (const float*)d_in[2];
    const float* W_gnn  = (const float*)d_in[3];
    const float* b_gnn  = (const float*)d_in[4];
    const float* W_g    = (const float*)d_in[5];
    const float* b_g    = (const float*)d_in[6];
    const float* W_age  = (const float*)d_in[7];
    const float* b_age  = (const float*)d_in[8];
    const float* W_occ  = (const float*)d_in[9];
    const float* b_occ  = (const float*)d_in[10];
    const int*   src    = (const int*)d_in[11];
    const int*   dst    = (const int*)d_in[12];
    const int*   nb     = (const int*)d_in[13];
    const int*   gender = (const int*)d_in[14];
    float* out = (float*)d_out;

    k_statsfill<<<K2_BLKS, 512>>>(E, src, dst, nb);
    k_tiles<<<TILE_BLKS, TNT>>>(E, gamma, beta, W_gnn, b_gnn, W_g, b_g,
                                W_age, b_age, W_occ, b_occ, nb, gender, out);
}

// round 17
// speedup vs baseline: 1.2858x; 1.0537x over previous
#include <cuda_runtime.h>
#include <math.h>

#define N_ENT   100000
#define D       128
#define N_EDGES 1600000
#define BATCH   8192
#define EPS     1e-5f

#define SLACK    128
#define BM_WORDS 3125              // ceil(100000/32)

#define NT2   1024                 // statsfill threads
#define FILL_BLKS 74
#define STAT_BLKS 221
#define K2_BLKS   (FILL_BLKS + STAT_BLKS + 1)   // 296 -> single wave @2/SM

#define TNT   1024                 // k_tiles threads
#define TROWS 32                   // rows per tile block (1 row per warp)
#define TILE_BLKS (BATCH / TROWS)  // 256 -> single wave @2/SM, 64 warps/SM

// output layout: [loss(1)] [age(8192*7)] [gender(8192)] [occ(8192*21)]
#define OFF_AGE  1
#define OFF_G    (1 + BATCH * 7)
#define OFF_OCC  (OFF_G + BATCH)

// ------------- persistent device state (zero-init; self-maintained) -------
__device__ __align__(16) float g_colsum[D];
__device__ __align__(16) float g_colsq[D];
__device__ __align__(16) float g_wfused[D * 32];   // fused head weights
__device__ unsigned g_bm[BM_WORDS];
__device__ int   g_slotmark[N_ENT];        // == epoch tag when claimed this replay
__device__ int   g_slotnum[N_ENT];         // compact slot for claimed nodes
__device__ int   g_epoch;                  // bumped by last tile block
__device__ int   g_nslots;
__device__ int   g_prep_cnt;               // fill-block prep barrier
__device__ int   g_cur[BATCH];             // slot cursor == degree
__device__ int   g_ebufc[BATCH * SLACK];   // compact buckets (4 MB)
__device__ float g_loss;                   // BCE accumulator
__device__ int   g_done;                   // tile completion counter

// ====== K1: prep+fill (blocks<74) || colstats (74..294) || fused-W (295) ==
__global__ void __launch_bounds__(NT2, 2)
k_statsfill(const float* __restrict__ E,
            const int* __restrict__ src, const int* __restrict__ dst,
            const int* __restrict__ nb,
            const float* __restrict__ Wg, const float* __restrict__ Wage,
            const float* __restrict__ Wocc) {
    __shared__ __align__(16) char s_raw[16384];
    int tid = threadIdx.x;

    if (blockIdx.x < FILL_BLKS) {
        // ---- phase A: cooperative prep (claim slots + bitmask) ----
        {
            const int per = (BATCH + FILL_BLKS - 1) / FILL_BLKS;   // 111
            int i0 = blockIdx.x * per;
            int i1 = i0 + per; if (i1 > BATCH) i1 = BATCH;
            int tag = g_epoch + 1;
            for (int i = i0 + tid; i < i1; i += NT2) {
                int node = nb[i];
                atomicOr(&g_bm[node >> 5], 1u << (node & 31));
                int old = atomicExch(&g_slotmark[node], tag);
                if (old != tag) {              // first claimer this replay
                    int s = atomicAdd(&g_nslots, 1);
                    g_slotnum[node] = s;
                }
            }
            __threadfence();
            __syncthreads();
            if (tid == 0) {
                atomicAdd(&g_prep_cnt, 1);
                while (*(volatile int*)&g_prep_cnt < FILL_BLKS) __nanosleep(32);
            }
            __syncthreads();
            __threadfence();                   // acquire: see all preps
        }

        // ---- phase B: filtered edge fill into compact buckets ----
        unsigned* s_bm = (unsigned*)s_raw;
        for (int i = tid; i < BM_WORDS; i += NT2) s_bm[i] = g_bm[i];
        __syncthreads();
        const int4* dst4 = (const int4*)dst;
        const int stride = FILL_BLKS * NT2;
        for (int idx4 = blockIdx.x * NT2 + tid; idx4 < N_EDGES / 4; idx4 += stride) {
            int4 d4 = dst4[idx4];
            int e = idx4 * 4;
            int dd[4] = {d4.x, d4.y, d4.z, d4.w};
#pragma unroll
            for (int k = 0; k < 4; k++) {
                int d = dd[k];
                if ((s_bm[d >> 5] >> (d & 31)) & 1u) {
                    int s = g_slotnum[d];
                    int p = atomicAdd(&g_cur[s], 1);
                    if (p < SLACK) g_ebufc[s * SLACK + p] = src[e + k];
                }
            }
        }
    } else if (blockIdx.x < FILL_BLKS + STAT_BLKS) {
        // ---- column stats partials -> float atomics (prep-independent) ----
        int cb = blockIdx.x - FILL_BLKS;
        const int rows_per = (N_ENT + STAT_BLKS - 1) / STAT_BLKS;   // 453
        int r0 = cb * rows_per;
        int r1 = r0 + rows_per; if (r1 > N_ENT) r1 = N_ENT;
        int c4 = tid & 31;
        int grp = tid >> 5;                // 0..31
        const float4* E4 = (const float4*)E;
        float4 s = make_float4(0.f, 0.f, 0.f, 0.f);
        float4 q = make_float4(0.f, 0.f, 0.f, 0.f);
#pragma unroll 8
        for (int r = r0 + grp; r < r1; r += 32) {
            float4 v = E4[(size_t)r * 32 + c4];
            s.x += v.x; s.y += v.y; s.z += v.z; s.w += v.w;
            q.x += v.x * v.x; q.y += v.y * v.y;
            q.z += v.z * v.z; q.w += v.w * v.w;
        }
        float4* s_red = (float4*)s_raw;    // [1024] float4 = 16 KB
        s_red[grp * 32 + c4] = s;
        __syncthreads();
        if (tid < 32) {
            float4 a = make_float4(0.f, 0.f, 0.f, 0.f);
#pragma unroll
            for (int g = 0; g < 32; g++) {
                float4 v = s_red[g * 32 + tid];
                a.x += v.x; a.y += v.y; a.z += v.z; a.w += v.w;
            }
            atomicAdd(&g_colsum[tid * 4 + 0], a.x);
            atomicAdd(&g_colsum[tid * 4 + 1], a.y);
            atomicAdd(&g_colsum[tid * 4 + 2], a.z);
            atomicAdd(&g_colsum[tid * 4 + 3], a.w);
        }
        __syncthreads();
        s_red[grp * 32 + c4] = q;
        __syncthreads();
        if (tid < 32) {
            float4 a = make_float4(0.f, 0.f, 0.f, 0.f);
#pragma unroll
            for (int g = 0; g < 32; g++) {
                float4 v = s_red[g * 32 + tid];
                a.x += v.x; a.y += v.y; a.z += v.z; a.w += v.w;
            }
            atomicAdd(&g_colsq[tid * 4 + 0], a.x);
            atomicAdd(&g_colsq[tid * 4 + 1], a.y);
            atomicAdd(&g_colsq[tid * 4 + 2], a.z);
            atomicAdd(&g_colsq[tid * 4 + 3], a.w);
        }
    } else {
        // ---- fused head-weight matrix precompute (once per replay) ----
        for (int i = tid; i < D * 32; i += NT2) {
            int k = i >> 5, c = i & 31;
            float w;
            if (c == 0)       w = Wg[k];
            else if (c < 8)   w = Wage[k * 7 + (c - 1)];
            else if (c < 29)  w = Wocc[k * 21 + (c - 8)];
            else              w = 0.0f;
            g_wfused[i] = w;
        }
    }
}

// ======== K2: fused gather + affine + GEMM + heads + loss + cleanup =======
__global__ void __launch_bounds__(TNT, 2)
k_tiles(const float* __restrict__ E,
        const float* __restrict__ gamma, const float* __restrict__ beta,
        const float* __restrict__ W_gnn, const float* __restrict__ b_gnn,
        const float* __restrict__ bg,
        const float* __restrict__ bage,  const float* __restrict__ bocc,
        const int* __restrict__ nb,      const int* __restrict__ gender,
        float* __restrict__ out) {
    __shared__ __align__(16) float sA[TROWS * D];     // 16 KB
    __shared__ __align__(16) float sU[TROWS * D];     // 16 KB
    __shared__ __align__(16) float sW[D * 32];        // 16 KB fused head weights
    __shared__ float s_scale[D];
    __shared__ float s_shift[D];
    __shared__ int   s_last;
    float4* sA4 = (float4*)sA;
    const int tid = threadIdx.x;
    const int lane = tid & 31;
    const int widx = tid >> 5;             // 0..31

    if (tid < D) {
        const float invn = 1.0f / (float)N_ENT;
        float mean = g_colsum[tid] * invn;
        float var = g_colsq[tid] * invn - mean * mean;
        float sc = rsqrtf(var + EPS) * gamma[tid];
        s_scale[tid] = sc;
        s_shift[tid] = beta[tid] - mean * sc;
    }
    // stage fused head weights: one coalesced float4 per thread
    ((float4*)sW)[tid] = ((const float4*)g_wfused)[tid];
    __syncthreads();

    const int row0 = blockIdx.x * TROWS;
    const int row = row0 + widx;           // one row per warp
    const float4* E4 = (const float4*)E;

    // gather raw neighbor sum + affine (MLP-4)
    {
        int node = nb[row];
        int s = g_slotnum[node];
        int deg = g_cur[s];
        int dc = deg < SLACK ? deg : SLACK;
        const int* lst = &g_ebufc[s * SLACK];
        float4 acc = make_float4(0.f, 0.f, 0.f, 0.f);
        int i = 0;
        for (; i + 4 <= dc; i += 4) {
            int i0 = lst[i + 0], i1 = lst[i + 1];
            int i2 = lst[i + 2], i3 = lst[i + 3];
            float4 a = E4[(size_t)i0 * 32 + lane];
            float4 b = E4[(size_t)i1 * 32 + lane];
            float4 c = E4[(size_t)i2 * 32 + lane];
            float4 d = E4[(size_t)i3 * 32 + lane];
            acc.x += a.x + b.x + c.x + d.x;
            acc.y += a.y + b.y + c.y + d.y;
            acc.z += a.z + b.z + c.z + d.z;
            acc.w += a.w + b.w + c.w + d.w;
        }
        for (; i < dc; i++) {
            int sv = lst[i];
            float4 a = E4[(size_t)sv * 32 + lane];
            acc.x += a.x; acc.y += a.y; acc.z += a.z; acc.w += a.w;
        }
        float fdeg = (float)deg;
        float inv = 1.0f / fmaxf(fdeg, 1.0f);
        float4 sc4 = ((const float4*)s_scale)[lane];
        float4 sh4 = ((const float4*)s_shift)[lane];
        float4 o;
        o.x = (acc.x * sc4.x + fdeg * sh4.x) * inv;
        o.y = (acc.y * sc4.y + fdeg * sh4.y) * inv;
        o.z = (acc.z * sc4.z + fdeg * sh4.z) * inv;
        o.w = (acc.w * sc4.w + fdeg * sh4.w) * inv;
        sA4[widx * 32 + lane] = o;
    }
    __syncthreads();

    // GEMM: col = tid&127, grp = tid>>7 (0..7): rows grp*4..grp*4+3
    {
        int col = tid & 127;
        int grp = tid >> 7;
        float accg[4] = {0.f, 0.f, 0.f, 0.f};
        for (int k = 0; k < D; k += 4) {
            float w0 = W_gnn[(k + 0) * D + col];
            float w1 = W_gnn[(k + 1) * D + col];
            float w2 = W_gnn[(k + 2) * D + col];
            float w3 = W_gnn[(k + 3) * D + col];
#pragma unroll
            for (int r = 0; r < 4; r++) {
                float4 a = *(const float4*)&sA[(grp * 4 + r) * D + k];
                accg[r] += a.x * w0 + a.y * w1 + a.z * w2 + a.w * w3;
            }
        }
        float bb = b_gnn[col];
#pragma unroll
        for (int r = 0; r < 4; r++)
            sU[(grp * 4 + r) * D + col] = fmaxf(accg[r] + bb, 0.0f);
    }
    __syncthreads();

    // heads as smem mini-GEMM: thread = (hrow = widx, hcol = lane)
    {
        int hcol = lane;                   // 0..31 (29 used)
        int hrow = widx;                   // 0..31
        const float4* u4 = (const float4*)&sU[hrow * D];
        float acc = 0.0f;
#pragma unroll
        for (int k4 = 0; k4 < D / 4; k4++) {
            float4 u = u4[k4];
            int k = k4 * 4;
            acc += u.x * sW[(k + 0) * 32 + hcol]
                 + u.y * sW[(k + 1) * 32 + hcol]
                 + u.z * sW[(k + 2) * 32 + hcol]
                 + u.w * sW[(k + 3) * 32 + hcol];
        }
        int orow = row0 + hrow;
        if (hcol == 0) {
            float x = acc + bg[0];
            out[OFF_G + orow] = x;
            float z = (float)gender[orow];
            float bce = fmaxf(x, 0.0f) - x * z + log1pf(expf(-fabsf(x)));
            atomicAdd(&g_loss, bce);       // no-return REDG, single address
        } else if (hcol < 8) {
            out[OFF_AGE + (size_t)orow * 7 + (hcol - 1)] = acc + bage[hcol - 1];
        } else if (hcol < 29) {
            out[OFF_OCC + (size_t)orow * 21 + (hcol - 8)] = acc + bocc[hcol - 8];
        }
    }
    __syncthreads();

    // last block: finish loss + cleanup for next replay
    if (tid == 0) {
        __threadfence();
        s_last = (atomicAdd(&g_done, 1) == TILE_BLKS - 1);
    }
    __syncthreads();
    if (s_last) {
        if (tid == 0) {
            __threadfence();
            out[0] = *(volatile float*)&g_loss * (1.0f / (float)BATCH);
            g_loss = 0.0f;
            g_nslots = 0;
            g_prep_cnt = 0;
            g_epoch = g_epoch + 1;
            g_done = 0;
        }
        for (int i = tid; i < BATCH; i += TNT) g_cur[i] = 0;
        for (int i = tid; i < BM_WORDS; i += TNT) g_bm[i] = 0;
        if (tid < D) { g_colsum[tid] = 0.0f; g_colsq[tid] = 0.0f; }
        __threadfence();
    }
}

// ---------------- launch ----------------
extern "C" void kernel_launch(void* const* d_in, const int* in_sizes, int n_in,
                              void* d_out, int out_size) {
    const float* E      = (const float*)d_in[0];
    const float* gamma  = (const float*)d_in[1];
    const float* beta   = (const float*)d_in[2];
    const float* W_gnn  = (const float*)d_in[3];
    const float* b_gnn  = (const float*)d_in[4];
    const float* W_g    = (const float*)d_in[5];
    const float* b_g    = (const float*)d_in[6];
    const float* W_age  = (const float*)d_in[7];
    const float* b_age  = (const float*)d_in[8];
    const float* W_occ  = (const float*)d_in[9];
    const float* b_occ  = (const float*)d_in[10];
    const int*   src    = (const int*)d_in[11];
    const int*   dst    = (const int*)d_in[12];
    const int*   nb     = (const int*)d_in[13];
    const int*   gender = (const int*)d_in[14];
    float* out = (float*)d_out;

    k_statsfill<<<K2_BLKS, NT2>>>(E, src, dst, nb, W_g, W_age, W_occ);
    k_tiles<<<TILE_BLKS, TNT>>>(E, gamma, beta, W_gnn, b_gnn, b_g,
                                b_age, b_occ, nb, gender, out);
}